// round 7
// baseline (speedup 1.0000x reference)
#include <cuda_runtime.h>
#include <cuda_bf16.h>

#define NB 16384
#define NF 26
#define FIELD_DIM 100000
#define WARPS_PER_CTA 8
#define NGROUPS (NB / WARPS_PER_CTA)   // 2048 groups of 8 rows
#define GRID 512                       // all-resident; each CTA does exactly 4 groups

__global__ __launch_bounds__(256) void mixdim_embbag_kernel(
    const int* __restrict__ x,
    const float* __restrict__ t0,
    const float* __restrict__ t1,
    const float* __restrict__ t2,
    const float* __restrict__ W1,
    const float* __restrict__ b1,
    const float* __restrict__ W2,
    const float* __restrict__ b2,
    float* __restrict__ out)
{
    __shared__ __align__(16) float sh1[WARPS_PER_CTA][32];   // block-1 sums per row
    __shared__ __align__(16) float sh2[WARPS_PER_CTA][16];   // block-2 sums per row
    __shared__ float sW1[64 * 33];                            // padded, conflict-free
    __shared__ float sW2[64 * 17];
    __shared__ float red[4][WARPS_PER_CTA][64];               // projection partials

    const int tid = threadIdx.x;
    const int w   = tid >> 5;           // warp -> row within group
    const int l   = tid & 31;

    // ---- Stage W1/W2 into shared ONCE per CTA lifetime ----
    #pragma unroll
    for (int i = 0; i < 8; ++i) {                 // W1: 64x32
        int idx = tid + 256 * i;
        int d = idx >> 5, j = idx & 31;
        sW1[d * 33 + j] = W1[idx];
    }
    #pragma unroll
    for (int i = 0; i < 4; ++i) {                 // W2: 64x16
        int idx = tid + 256 * i;
        int d = idx >> 4, j = idx & 15;
        sW2[d * 17 + j] = W2[idx];
    }
    // bias (zero in dataset; kept exact): each lane's two output dims
    const float2 bb1 = reinterpret_cast<const float2*>(b1)[l];
    const float2 bb2 = reinterpret_cast<const float2*>(b2)[l];
    __syncthreads();

    for (int grp = blockIdx.x; grp < NGROUPS; grp += GRID) {
        const int row = grp * WARPS_PER_CTA + w;

        // ---- Gather phase: one warp per row, all 21 loads batched ----
        int xi = 0;
        if (l < NF) xi = x[row * NF + l];

        int i0[8], i1[8], i2[5];
        #pragma unroll
        for (int f = 0; f < 8; ++f)
            i0[f] = __shfl_sync(0xffffffffu, xi, f) + f * FIELD_DIM;
        #pragma unroll
        for (int f = 0; f < 8; ++f)
            i1[f] = __shfl_sync(0xffffffffu, xi, 8 + f) + f * FIELD_DIM;
        const int half = l >> 4;
        #pragma unroll
        for (int p = 0; p < 5; ++p) {
            int fld = 2 * p + half;
            i2[p] = __shfl_sync(0xffffffffu, xi, 16 + fld) + fld * FIELD_DIM;
        }

        float2 v0[8];
        float  v1[8];
        float  v2[5];
        const float2* t0v = reinterpret_cast<const float2*>(t0);
        const int l16 = l & 15;
        #pragma unroll
        for (int f = 0; f < 8; ++f) v0[f] = __ldg(&t0v[i0[f] * 32 + l]);
        #pragma unroll
        for (int f = 0; f < 8; ++f) v1[f] = __ldg(&t1[i1[f] * 32 + l]);
        #pragma unroll
        for (int p = 0; p < 5; ++p) v2[p] = __ldg(&t2[i2[p] * 16 + l16]);

        float2 acc = make_float2(0.f, 0.f);
        #pragma unroll
        for (int f = 0; f < 8; ++f) { acc.x += v0[f].x; acc.y += v0[f].y; }
        float s1 = 0.f;
        #pragma unroll
        for (int f = 0; f < 8; ++f) s1 += v1[f];
        float s2 = 0.f;
        #pragma unroll
        for (int p = 0; p < 5; ++p) s2 += v2[p];
        s2 += __shfl_xor_sync(0xffffffffu, s2, 16);

        sh1[w][l] = s1;
        if (l < 16) sh2[w][l] = s2;
        __syncthreads();

        // ---- Projection: thread (d, q) applies its 12 weights to all 8 rows ----
        {
            const int d = tid & 63;
            const int q = tid >> 6;
            float wr1[8], wr2[4];
            #pragma unroll
            for (int j = 0; j < 8; ++j) wr1[j] = sW1[d * 33 + 8 * q + j];
            #pragma unroll
            for (int j = 0; j < 4; ++j) wr2[j] = sW2[d * 17 + 4 * q + j];
            #pragma unroll
            for (int r = 0; r < WARPS_PER_CTA; ++r) {
                float p = 0.f;
                #pragma unroll
                for (int j = 0; j < 8; ++j) p += wr1[j] * sh1[r][8 * q + j];
                #pragma unroll
                for (int j = 0; j < 4; ++j) p += wr2[j] * sh2[r][4 * q + j];
                red[q][r][d] = p;
            }
        }
        __syncthreads();

        // ---- Combine on the (w, l) mapping that still holds acc in regs ----
        float2 pr = make_float2(0.f, 0.f);
        #pragma unroll
        for (int qq = 0; qq < 4; ++qq) {
            pr.x += red[qq][w][2 * l];
            pr.y += red[qq][w][2 * l + 1];
        }
        acc.x += pr.x + 8.f * bb1.x + 10.f * bb2.x;
        acc.y += pr.y + 8.f * bb1.y + 10.f * bb2.y;

        reinterpret_cast<float2*>(out)[row * 32 + l] = acc;
    }
}

extern "C" void kernel_launch(void* const* d_in, const int* in_sizes, int n_in,
                              void* d_out, int out_size) {
    const int*   x  = (const int*)  d_in[0];
    const float* t0 = (const float*)d_in[1];
    const float* t1 = (const float*)d_in[2];
    const float* t2 = (const float*)d_in[3];
    const float* W1 = (const float*)d_in[4];
    const float* b1 = (const float*)d_in[5];
    const float* W2 = (const float*)d_in[6];
    const float* b2 = (const float*)d_in[7];
    float* out = (float*)d_out;

    mixdim_embbag_kernel<<<GRID, 32 * WARPS_PER_CTA>>>(x, t0, t1, t2, W1, b1, W2, b2, out);
}

// round 10
// speedup vs baseline: 1.0840x; 1.0840x over previous
#include <cuda_runtime.h>
#include <cuda_bf16.h>

#define NB 16384
#define NF 26
#define FIELD_DIM 100000
#define WARPS_PER_CTA 8

__global__ __launch_bounds__(256) void mixdim_embbag_kernel(
    const int* __restrict__ x,
    const float* __restrict__ t0,
    const float* __restrict__ t1,
    const float* __restrict__ t2,
    const float* __restrict__ W1,
    const float* __restrict__ b1,
    const float* __restrict__ W2,
    const float* __restrict__ b2,
    float* __restrict__ out)
{
    // stride-36 / stride-20 padding: float4-aligned (144B / 80B rows) AND
    // conflict-free within each quarter-warp phase of LDS.128.
    __shared__ __align__(16) float sW1[64 * 36];
    __shared__ __align__(16) float sW2[64 * 20];
    __shared__ __align__(16) float sh0[WARPS_PER_CTA][64];  // block-0 sums
    __shared__ __align__(16) float sh1[WARPS_PER_CTA][32];  // block-1 sums
    __shared__ __align__(16) float sh2[WARPS_PER_CTA][16];  // block-2 sums

    const int tid = threadIdx.x;
    const int w   = tid >> 5;          // warp -> row within group
    const int l   = tid & 31;
    const int row = blockIdx.x * WARPS_PER_CTA + w;

    // ---- Stage W1/W2 into shared (coalesced; overlaps with gathers below) ----
    #pragma unroll
    for (int i = 0; i < 8; ++i) {                 // W1: 64x32
        int idx = tid + 256 * i;
        sW1[(idx >> 5) * 36 + (idx & 31)] = W1[idx];
    }
    #pragma unroll
    for (int i = 0; i < 4; ++i) {                 // W2: 64x16
        int idx = tid + 256 * i;
        sW2[(idx >> 4) * 20 + (idx & 15)] = W2[idx];
    }
    // bias for this thread's output dim (sums to nb*b; zero in dataset, kept exact)
    const int d  = tid & 63;
    const int rb = tid >> 6;
    const float bd = 8.f * __ldg(&b1[d]) + 10.f * __ldg(&b2[d]);

    // ---- Gather phase: one warp per row, all 21 loads batched ----
    int xi = 0;
    if (l < NF) xi = x[row * NF + l];

    int i0[8], i1[8], i2[5];
    #pragma unroll
    for (int f = 0; f < 8; ++f)
        i0[f] = __shfl_sync(0xffffffffu, xi, f) + f * FIELD_DIM;
    #pragma unroll
    for (int f = 0; f < 8; ++f)
        i1[f] = __shfl_sync(0xffffffffu, xi, 8 + f) + f * FIELD_DIM;
    const int half = l >> 4;
    #pragma unroll
    for (int p = 0; p < 5; ++p) {
        int fld = 2 * p + half;
        i2[p] = __shfl_sync(0xffffffffu, xi, 16 + fld) + fld * FIELD_DIM;
    }

    float2 v0[8];
    float  v1[8];
    float  v2[5];
    const float2* t0v = reinterpret_cast<const float2*>(t0);
    const int l16 = l & 15;
    #pragma unroll
    for (int f = 0; f < 8; ++f) v0[f] = __ldg(&t0v[i0[f] * 32 + l]);
    #pragma unroll
    for (int f = 0; f < 8; ++f) v1[f] = __ldg(&t1[i1[f] * 32 + l]);
    #pragma unroll
    for (int p = 0; p < 5; ++p) v2[p] = __ldg(&t2[i2[p] * 16 + l16]);

    float2 acc = make_float2(0.f, 0.f);
    #pragma unroll
    for (int f = 0; f < 8; ++f) { acc.x += v0[f].x; acc.y += v0[f].y; }
    float s1 = 0.f;
    #pragma unroll
    for (int f = 0; f < 8; ++f) s1 += v1[f];
    float s2 = 0.f;
    #pragma unroll
    for (int p = 0; p < 5; ++p) s2 += v2[p];
    s2 += __shfl_xor_sync(0xffffffffu, s2, 16);   // combine even/odd-field halves

    reinterpret_cast<float2*>(&sh0[w][0])[l] = acc;
    sh1[w][l] = s1;
    if (l < 16) sh2[w][l] = s2;
    __syncthreads();

    // ---- Projection + direct store: thread (rb, d) owns rows rb and rb+4 ----
    const float4* w1v = reinterpret_cast<const float4*>(&sW1[d * 36]);
    const float4* w2v = reinterpret_cast<const float4*>(&sW2[d * 20]);
    #pragma unroll
    for (int rr = 0; rr < 2; ++rr) {
        const int r = rb + 4 * rr;
        const float4* s1v = reinterpret_cast<const float4*>(&sh1[r][0]);
        const float4* s2v = reinterpret_cast<const float4*>(&sh2[r][0]);
        float p = sh0[r][d] + bd;
        #pragma unroll
        for (int j = 0; j < 8; ++j) {
            float4 wv = w1v[j], sv = s1v[j];
            p += wv.x * sv.x + wv.y * sv.y + wv.z * sv.z + wv.w * sv.w;
        }
        #pragma unroll
        for (int j = 0; j < 4; ++j) {
            float4 wv = w2v[j], sv = s2v[j];
            p += wv.x * sv.x + wv.y * sv.y + wv.z * sv.z + wv.w * sv.w;
        }
        out[(blockIdx.x * WARPS_PER_CTA + r) * 64 + d] = p;
    }
}

extern "C" void kernel_launch(void* const* d_in, const int* in_sizes, int n_in,
                              void* d_out, int out_size) {
    const int*   x  = (const int*)  d_in[0];
    const float* t0 = (const float*)d_in[1];
    const float* t1 = (const float*)d_in[2];
    const float* t2 = (const float*)d_in[3];
    const float* W1 = (const float*)d_in[4];
    const float* b1 = (const float*)d_in[5];
    const float* W2 = (const float*)d_in[6];
    const float* b2 = (const float*)d_in[7];
    float* out = (float*)d_out;

    dim3 grid(NB / WARPS_PER_CTA);   // 2048 CTAs, one 8-row group each
    dim3 block(32 * WARPS_PER_CTA);
    mixdim_embbag_kernel<<<grid, block>>>(x, t0, t1, t2, W1, b1, W2, b2, out);
}